// round 14
// baseline (speedup 1.0000x reference)
#include <cuda_runtime.h>
#include <math_constants.h>
#include <cstdint>

// Problem constants
#define BB   4
#define TT   4096
#define DIN  1024
#define HH   16
#define DD   64
#define MM   (BB*TT)      // 16384
#define NN   (HH*DD*2)    // 2048
#define HD   (HH*DD)      // 1024

// scan chunking
#define NCH  32
#define TC   (TT/NCH)     // 128

// GEMM tiling: CTA 128x128, 4 warps (2x2), warp tile 64x64, ldmatrix + padded smem
// BK=8 / TS=12 -> 25KB smem/CTA -> 4 CTAs/SM (occupancy lever)
#define Bb_M 128
#define Bb_N 128
#define BB_K 8
#define GT   128
#define TS   12                      // smem row stride (8 + 4 pad), floats
#define TILE_FLOATS (128*TS)         // 1536 floats = 6KB per tile buffer

// ---------------- scratch (device globals; referenced from device code ONLY) ----------------
__device__ float g_Atf[(size_t)MM * DIN];  // 64 MB tf32-RNA inputs
__device__ float g_Wt [(size_t)NN * DIN];  // 8 MB  tf32-RNA weights, transposed [N,K]
__device__ float g_V[(size_t)MM * HD];     // 64 MB
__device__ float g_ST[(size_t)MM * HH];    // 1 MB
__device__ float g_AggM[BB*HH*NCH];
__device__ float g_AggU[BB*HH*NCH];
__device__ float g_AggW[BB*HH*NCH*DD];
__device__ float g_PreM[BB*HH*NCH];
__device__ float g_PreU[BB*HH*NCH];
__device__ float g_PreW[BB*HH*NCH*DD];

// ---------------- helpers ----------------
__device__ __forceinline__ float tf32_rna(float x) {
    uint32_t u;
    asm("cvt.rna.tf32.f32 %0, %1;" : "=r"(u) : "f"(x));
    return __uint_as_float(u);
}
__device__ __forceinline__ void cp_async16(uint32_t saddr, const void* gptr) {
    asm volatile("cp.async.ca.shared.global [%0], [%1], 16;\n" :: "r"(saddr), "l"(gptr));
}
#define CP_COMMIT() asm volatile("cp.async.commit_group;\n")

__device__ __forceinline__ void ldsm_x4(uint32_t* r, uint32_t addr) {
    asm volatile("ldmatrix.sync.aligned.m8n8.x4.shared.b16 {%0,%1,%2,%3}, [%4];"
                 : "=r"(r[0]), "=r"(r[1]), "=r"(r[2]), "=r"(r[3]) : "r"(addr));
}

// ---------------- zero output ----------------
__global__ void zero_kernel(float* __restrict__ out, int n) {
    int i = blockIdx.x * blockDim.x + threadIdx.x;
    if (i < n) out[i] = 0.0f;
}

// ---------------- tf32 RNA preprocessing ----------------
__global__ __launch_bounds__(256) void round_tf32_A(const float* __restrict__ in)
{
    int i = blockIdx.x * blockDim.x + threadIdx.x;
    float4 v = ((const float4*)in)[i];
    v.x = tf32_rna(v.x); v.y = tf32_rna(v.y);
    v.z = tf32_rna(v.z); v.w = tf32_rna(v.w);
    ((float4*)g_Atf)[i] = v;
}

// transpose + RNA-round W [DIN, NN] -> g_Wt [NN, DIN]
__global__ __launch_bounds__(256) void transW_kernel(const float* __restrict__ W)
{
    __shared__ float t[32][33];
    const int n0 = blockIdx.x * 32;
    const int k0 = blockIdx.y * 32;
    const int tx = threadIdx.x & 31;
    const int ty = threadIdx.x >> 5;   // 0..7
#pragma unroll
    for (int i = 0; i < 4; ++i)
        t[ty + i * 8][tx] = tf32_rna(W[(size_t)(k0 + ty + i * 8) * NN + n0 + tx]);
    __syncthreads();
#pragma unroll
    for (int i = 0; i < 4; ++i)
        g_Wt[(size_t)(n0 + ty + i * 8) * DIN + k0 + tx] = t[tx][ty + i * 8];
}

// ---------------- tensor GEMM + fused st: kv = relu(A@W), st = q.K ----------------
__global__ __launch_bounds__(GT) void gemm_tc_kernel(const float* __restrict__ qk)
{
    __shared__ __align__(16) float As[2][TILE_FLOATS];
    __shared__ __align__(16) float Bs[2][TILE_FLOATS];
    __shared__ float stPart[2][Bb_M];   // per-wn partial q.K sums

    const int tid  = threadIdx.x;
    const int wid  = tid >> 5;
    const int lane = tid & 31;
    const int g    = lane >> 2;      // 0..7
    const int tg   = lane & 3;       // 0..3
    const int wm   = wid & 1;        // warp M (0..1) -> 64 rows
    const int wn   = wid >> 1;       // warp N (0..1) -> 64 cols
    const int m0   = blockIdx.y * Bb_M;
    const int n0   = blockIdx.x * Bb_N;

    const float* Ab = g_Atf + (size_t)m0 * DIN;
    const float* Bg = g_Wt  + (size_t)n0 * DIN;

    // cp.async mapping: 2 threads per row (16B each), 64 rows per pass, 2 passes
    const int lrow = tid >> 1;           // 0..63
    const int lcol = (tid & 1) * 4;      // 0,4

    // ldmatrix per-lane offsets (same distribution as proven rounds; TS changed)
    const int a_row = (lane & 7) + ((lane & 8)  ? 8 : 0);
    const int a_col = (lane & 16) ? 4 : 0;
    const int b_row = (lane & 7) + ((lane & 16) ? 8 : 0);
    const int b_col = (lane & 8)  ? 4 : 0;
    const uint32_t as_base = (uint32_t)__cvta_generic_to_shared(&As[0][0]);
    const uint32_t bs_base = (uint32_t)__cvta_generic_to_shared(&Bs[0][0]);
    const int a_off = (wm * 64 + a_row) * TS + a_col;
    const int b_off = (wn * 64 + b_row) * TS + b_col;

    float acc[4][8][4];
#pragma unroll
    for (int i = 0; i < 4; ++i)
#pragma unroll
        for (int j = 0; j < 8; ++j)
#pragma unroll
            for (int r = 0; r < 4; ++r) acc[i][j][r] = 0.0f;

    auto load_stage = [&](int s, int k0) {
        uint32_t ab = (uint32_t)__cvta_generic_to_shared(&As[s][0]);
        uint32_t bb = (uint32_t)__cvta_generic_to_shared(&Bs[s][0]);
#pragma unroll
        for (int p = 0; p < 2; ++p) {
            const int r = lrow + p * 64;
            cp_async16(ab + (r * TS + lcol) * 4, Ab + (size_t)r * DIN + k0 + lcol);
            cp_async16(bb + (r * TS + lcol) * 4, Bg + (size_t)r * DIN + k0 + lcol);
        }
        CP_COMMIT();
    };

    load_stage(0, 0);

    const int NIT = DIN / BB_K;   // 128
#pragma unroll 1
    for (int it = 0; it < NIT; ++it) {
        const int s = it & 1;
        asm volatile("cp.async.wait_group 0;\n");   // stage `it` load complete
        __syncthreads();                            // visible; prior compute of s^1 done
        if (it + 1 < NIT) load_stage(s ^ 1, (it + 1) * BB_K);   // overlaps compute below

        const uint32_t abase = as_base + (uint32_t)(s * TILE_FLOATS + a_off) * 4;
        const uint32_t bbase = bs_base + (uint32_t)(s * TILE_FLOATS + b_off) * 4;

        uint32_t a[4][4], b[4][4];
#pragma unroll
        for (int i = 0; i < 4; ++i)
            ldsm_x4(a[i], abase + (uint32_t)(i * 16 * TS) * 4);
#pragma unroll
        for (int j2 = 0; j2 < 4; ++j2)
            ldsm_x4(b[j2], bbase + (uint32_t)(j2 * 16 * TS) * 4);
#pragma unroll
        for (int i = 0; i < 4; ++i)
#pragma unroll
            for (int j = 0; j < 8; ++j)
                asm volatile(
                    "mma.sync.aligned.m16n8k8.row.col.f32.tf32.tf32.f32 "
                    "{%0,%1,%2,%3}, {%4,%5,%6,%7}, {%8,%9}, {%0,%1,%2,%3};"
                    : "+f"(acc[i][j][0]), "+f"(acc[i][j][1]),
                      "+f"(acc[i][j][2]), "+f"(acc[i][j][3])
                    : "r"(a[i][0]), "r"(a[i][1]), "r"(a[i][2]), "r"(a[i][3]),
                      "r"(b[j >> 1][2 * (j & 1)]), "r"(b[j >> 1][2 * (j & 1) + 1]));
    }

    // ---- fused epilogue: relu, V store, st = q.K (this CTA is exactly head h) ----
    const int h  = n0 >> 7;                      // one head per CTA column-tile
    const int cb = (n0 >> 1) + wn * 32 + tg;     // K/V col of frag j=0
    float qv[8];
#pragma unroll
    for (int j = 0; j < 8; ++j)
        qv[j] = qk[h * DD + wn * 32 + tg + j * 4];

#pragma unroll
    for (int i = 0; i < 4; ++i) {
        const size_t r0 = (size_t)(m0 + wm * 64 + i * 16 + g);
        const size_t r1 = r0 + 8;
        float s0 = 0.0f, s1 = 0.0f;
#pragma unroll
        for (int j = 0; j < 8; ++j) {
            const int c = cb + j * 4;
            const float k0 = fmaxf(acc[i][j][0], 0.0f);
            const float v0 = fmaxf(acc[i][j][1], 0.0f);
            const float k1 = fmaxf(acc[i][j][2], 0.0f);
            const float v1 = fmaxf(acc[i][j][3], 0.0f);
            g_V[r0 * HD + c] = v0;
            g_V[r1 * HD + c] = v1;
            s0 = fmaf(k0, qv[j], s0);
            s1 = fmaf(k1, qv[j], s1);
        }
        // reduce over tg quad (lane bits 0,1)
        s0 += __shfl_xor_sync(0xffffffffu, s0, 1);
        s0 += __shfl_xor_sync(0xffffffffu, s0, 2);
        s1 += __shfl_xor_sync(0xffffffffu, s1, 1);
        s1 += __shfl_xor_sync(0xffffffffu, s1, 2);
        if (tg == i) {
            stPart[wn][wm * 64 + i * 16 + g]     = s0;
            stPart[wn][wm * 64 + i * 16 + 8 + g] = s1;
        }
    }
    __syncthreads();
    if (tid < Bb_M)
        g_ST[(size_t)(m0 + tid) * HH + h] = stPart[0][tid] + stPart[1][tid];
}

// ---------------- scan combine step ----------------
__device__ __forceinline__ void scan_step(float& m, float& u, float& w, float s, float v)
{
    float mn = fmaxf(m, s);
    float sc = __expf(m - mn);
    float e  = __expf(s - mn);
    u = u * sc + e;
    w = w * sc + e * v;
    m = mn;
}

// ---------------- pass A: per-chunk aggregates ----------------
__global__ __launch_bounds__(64) void passA_kernel()
{
    const int chain = blockIdx.y;
    const int chunk = blockIdx.x;
    const int d     = threadIdx.x;
    const int b = chain >> 4, h = chain & 15;

    float m = -CUDART_INF_F, u = 0.0f, w = 0.0f;
    const int t0 = chunk * TC;
#pragma unroll 4
    for (int t = t0; t < t0 + TC; ++t) {
        const size_t row = (size_t)b * TT + t;
        float s = g_ST[row * HH + h];
        float v = g_V[row * HD + h * DD + d];
        scan_step(m, u, w, s, v);
    }
    const int idx = chain * NCH + chunk;
    if (d == 0) { g_AggM[idx] = m; g_AggU[idx] = u; }
    g_AggW[idx * DD + d] = w;
}

// ---------------- pass B: exclusive prefix over chunks ----------------
__global__ __launch_bounds__(64) void passB_kernel()
{
    const int chain = blockIdx.x;
    const int d     = threadIdx.x;
    float m = -CUDART_INF_F, u = 0.0f, w = 0.0f;
    for (int c = 0; c < NCH; ++c) {
        const int idx = chain * NCH + c;
        if (d == 0) { g_PreM[idx] = m; g_PreU[idx] = u; }
        g_PreW[idx * DD + d] = w;
        float mb = g_AggM[idx], ub = g_AggU[idx], wb = g_AggW[idx * DD + d];
        float mn = fmaxf(m, mb);
        float ea = __expf(m - mn);
        float eb = __expf(mb - mn);
        u = u * ea + ub * eb;
        w = w * ea + wb * eb;
        m = mn;
    }
}

// ---------------- pass C: re-scan with prefix, head-sum via atomics ----------------
__global__ __launch_bounds__(64) void passC_kernel(float* __restrict__ out)
{
    const int chain = blockIdx.y;
    const int chunk = blockIdx.x;
    const int d     = threadIdx.x;
    const int b = chain >> 4, h = chain & 15;

    const int idx = chain * NCH + chunk;
    float m = g_PreM[idx];
    float u = g_PreU[idx];
    float w = g_PreW[idx * DD + d];

    const int t0 = chunk * TC;
#pragma unroll 4
    for (int t = t0; t < t0 + TC; ++t) {
        const size_t row = (size_t)b * TT + t;
        float s = g_ST[row * HH + h];
        float v = g_V[row * HD + h * DD + d];
        scan_step(m, u, w, s, v);
        atomicAdd(out + row * DD + d, w / u);
    }
}

// ---------------- launch ----------------
extern "C" void kernel_launch(void* const* d_in, const int* in_sizes, int n_in,
                              void* d_out, int out_size)
{
    const float* inputs = (const float*)d_in[0];   // [4,4096,1024]
    const float* kvk    = (const float*)d_in[1];   // [1024,2048]
    const float* qk     = (const float*)d_in[2];   // [16,64]
    float* out = (float*)d_out;                    // [4,4096,64]

    zero_kernel<<<(out_size + 255) / 256, 256>>>(out, out_size);

    round_tf32_A<<<(MM * DIN / 4) / 256, 256>>>(inputs);
    {
        dim3 tg(NN / 32, DIN / 32);                // (64, 32)
        transW_kernel<<<tg, 256>>>(kvk);
    }

    dim3 ggrid(NN / Bb_N, MM / Bb_M);              // (16, 128)
    gemm_tc_kernel<<<ggrid, GT>>>(qk);

    dim3 sgrid(NCH, BB * HH);                      // (32, 64)
    passA_kernel<<<sgrid, 64>>>();
    passB_kernel<<<BB * HH, 64>>>();
    passC_kernel<<<sgrid, 64>>>(out);
}

// round 15
// speedup vs baseline: 1.4464x; 1.4464x over previous
#include <cuda_runtime.h>
#include <math_constants.h>
#include <cstdint>

// Problem constants
#define BB   4
#define TT   4096
#define DIN  1024
#define HH   16
#define DD   64
#define MM   (BB*TT)      // 16384
#define NN   (HH*DD*2)    // 2048
#define HD   (HH*DD)      // 1024

// scan chunking
#define NCH  32
#define TC   (TT/NCH)     // 128

// GEMM tiling: CTA 128x128, 4 warps (2x2), warp tile 64x64, ldmatrix + padded smem
#define Bb_M 128
#define Bb_N 128
#define BB_K 16
#define GT   128
#define TS   20                      // smem row stride (16 + 4 pad), floats  [round-10/13 proven]
#define TILE_FLOATS (128*TS)         // 2560 floats per tile buffer

// ---------------- scratch (device globals; referenced from device code ONLY) ----------------
__device__ float g_Atf[(size_t)MM * DIN];  // 64 MB tf32-RNA inputs
__device__ float g_Wt [(size_t)NN * DIN];  // 8 MB  tf32-RNA weights, transposed [N,K]
__device__ float g_V[(size_t)MM * HD];     // 64 MB
__device__ float g_ST[(size_t)MM * HH];    // 1 MB
__device__ float g_AggM[BB*HH*NCH];
__device__ float g_AggU[BB*HH*NCH];
__device__ float g_AggW[BB*HH*NCH*DD];
__device__ float g_PreM[BB*HH*NCH];
__device__ float g_PreU[BB*HH*NCH];
__device__ float g_PreW[BB*HH*NCH*DD];

// ---------------- helpers ----------------
__device__ __forceinline__ float tf32_rna(float x) {
    uint32_t u;
    asm("cvt.rna.tf32.f32 %0, %1;" : "=r"(u) : "f"(x));
    return __uint_as_float(u);
}
__device__ __forceinline__ void cp_async16(uint32_t saddr, const void* gptr) {
    asm volatile("cp.async.ca.shared.global [%0], [%1], 16;\n" :: "r"(saddr), "l"(gptr));
}
#define CP_COMMIT() asm volatile("cp.async.commit_group;\n")

__device__ __forceinline__ void ldsm_x4(uint32_t* r, uint32_t addr) {
    asm volatile("ldmatrix.sync.aligned.m8n8.x4.shared.b16 {%0,%1,%2,%3}, [%4];"
                 : "=r"(r[0]), "=r"(r[1]), "=r"(r[2]), "=r"(r[3]) : "r"(addr));
}

// ---------------- zero output ----------------
__global__ void zero_kernel(float* __restrict__ out, int n) {
    int i = blockIdx.x * blockDim.x + threadIdx.x;
    if (i < n) out[i] = 0.0f;
}

// ---------------- tf32 RNA preprocessing ----------------
__global__ __launch_bounds__(256) void round_tf32_A(const float* __restrict__ in)
{
    int i = blockIdx.x * blockDim.x + threadIdx.x;
    float4 v = ((const float4*)in)[i];
    v.x = tf32_rna(v.x); v.y = tf32_rna(v.y);
    v.z = tf32_rna(v.z); v.w = tf32_rna(v.w);
    ((float4*)g_Atf)[i] = v;
}

// transpose + RNA-round W [DIN, NN] -> g_Wt [NN, DIN]
__global__ __launch_bounds__(256) void transW_kernel(const float* __restrict__ W)
{
    __shared__ float t[32][33];
    const int n0 = blockIdx.x * 32;
    const int k0 = blockIdx.y * 32;
    const int tx = threadIdx.x & 31;
    const int ty = threadIdx.x >> 5;   // 0..7
#pragma unroll
    for (int i = 0; i < 4; ++i)
        t[ty + i * 8][tx] = tf32_rna(W[(size_t)(k0 + ty + i * 8) * NN + n0 + tx]);
    __syncthreads();
#pragma unroll
    for (int i = 0; i < 4; ++i)
        g_Wt[(size_t)(n0 + ty + i * 8) * DIN + k0 + tx] = t[tx][ty + i * 8];
}

// ---------------- tensor GEMM + fused st: kv = relu(A@W), st = q.K ----------------
// __launch_bounds__(128, 3): force regs <= 170 so 3 CTAs/SM fit (RF was the occ limiter)
__global__ __launch_bounds__(GT, 3) void gemm_tc_kernel(const float* __restrict__ qk)
{
    __shared__ __align__(16) float As[2][TILE_FLOATS];
    __shared__ __align__(16) float Bs[2][TILE_FLOATS];
    __shared__ float stPart[2][Bb_M];   // per-wn partial q.K sums

    const int tid  = threadIdx.x;
    const int wid  = tid >> 5;
    const int lane = tid & 31;
    const int g    = lane >> 2;      // 0..7
    const int tg   = lane & 3;       // 0..3
    const int wm   = wid & 1;        // warp M (0..1) -> 64 rows
    const int wn   = wid >> 1;       // warp N (0..1) -> 64 cols
    const int m0   = blockIdx.y * Bb_M;
    const int n0   = blockIdx.x * Bb_N;

    const float* Ab = g_Atf + (size_t)m0 * DIN;
    const float* Bg = g_Wt  + (size_t)n0 * DIN;

    // cp.async mapping: 4 threads per row, 32 rows per pass, 4 passes
    const int lrow = tid >> 2;           // 0..31
    const int lcol = (tid & 3) * 4;      // 0,4,8,12

    // ldmatrix per-lane offsets (round-10/13 proven)
    const int a_row = (lane & 7) + ((lane & 8)  ? 8 : 0);
    const int a_col = (lane & 16) ? 4 : 0;
    const int b_row = (lane & 7) + ((lane & 16) ? 8 : 0);
    const int b_col = (lane & 8)  ? 4 : 0;
    const uint32_t as_base = (uint32_t)__cvta_generic_to_shared(&As[0][0]);
    const uint32_t bs_base = (uint32_t)__cvta_generic_to_shared(&Bs[0][0]);
    const int a_off = (wm * 64 + a_row) * TS + a_col;
    const int b_off = (wn * 64 + b_row) * TS + b_col;

    float acc[4][8][4];
#pragma unroll
    for (int i = 0; i < 4; ++i)
#pragma unroll
        for (int j = 0; j < 8; ++j)
#pragma unroll
            for (int r = 0; r < 4; ++r) acc[i][j][r] = 0.0f;

    auto load_stage = [&](int s, int k0) {
        uint32_t ab = (uint32_t)__cvta_generic_to_shared(&As[s][0]);
        uint32_t bb = (uint32_t)__cvta_generic_to_shared(&Bs[s][0]);
#pragma unroll
        for (int p = 0; p < 4; ++p) {
            const int r = lrow + p * 32;
            cp_async16(ab + (r * TS + lcol) * 4, Ab + (size_t)r * DIN + k0 + lcol);
            cp_async16(bb + (r * TS + lcol) * 4, Bg + (size_t)r * DIN + k0 + lcol);
        }
        CP_COMMIT();
    };

    load_stage(0, 0);

    const int NIT = DIN / BB_K;   // 64
#pragma unroll 1
    for (int it = 0; it < NIT; ++it) {
        const int s = it & 1;
        asm volatile("cp.async.wait_group 0;\n");   // stage `it` load complete
        __syncthreads();                            // visible; prior compute of s^1 done
        if (it + 1 < NIT) load_stage(s ^ 1, (it + 1) * BB_K);   // overlaps compute below

        const uint32_t abase = as_base + (uint32_t)(s * TILE_FLOATS + a_off) * 4;
        const uint32_t bbase = bs_base + (uint32_t)(s * TILE_FLOATS + b_off) * 4;

#pragma unroll
        for (int kc = 0; kc < 2; ++kc) {
            uint32_t a[4][4], b[4][4];
#pragma unroll
            for (int i = 0; i < 4; ++i)
                ldsm_x4(a[i], abase + (uint32_t)(i * 16 * TS + kc * 8) * 4);
#pragma unroll
            for (int j2 = 0; j2 < 4; ++j2)
                ldsm_x4(b[j2], bbase + (uint32_t)(j2 * 16 * TS + kc * 8) * 4);
#pragma unroll
            for (int i = 0; i < 4; ++i)
#pragma unroll
                for (int j = 0; j < 8; ++j)
                    asm volatile(
                        "mma.sync.aligned.m16n8k8.row.col.f32.tf32.tf32.f32 "
                        "{%0,%1,%2,%3}, {%4,%5,%6,%7}, {%8,%9}, {%0,%1,%2,%3};"
                        : "+f"(acc[i][j][0]), "+f"(acc[i][j][1]),
                          "+f"(acc[i][j][2]), "+f"(acc[i][j][3])
                        : "r"(a[i][0]), "r"(a[i][1]), "r"(a[i][2]), "r"(a[i][3]),
                          "r"(b[j >> 1][2 * (j & 1)]), "r"(b[j >> 1][2 * (j & 1) + 1]));
        }
    }

    // ---- fused epilogue: relu, V store, st = q.K (this CTA is exactly head h) ----
    const int h  = n0 >> 7;                      // one head per CTA column-tile
    const int cb = (n0 >> 1) + wn * 32 + tg;     // K/V col of frag j=0
    float qv[8];
#pragma unroll
    for (int j = 0; j < 8; ++j)
        qv[j] = qk[h * DD + wn * 32 + tg + j * 4];

#pragma unroll
    for (int i = 0; i < 4; ++i) {
        const size_t r0 = (size_t)(m0 + wm * 64 + i * 16 + g);
        const size_t r1 = r0 + 8;
        float s0 = 0.0f, s1 = 0.0f;
#pragma unroll
        for (int j = 0; j < 8; ++j) {
            const int c = cb + j * 4;
            const float k0 = fmaxf(acc[i][j][0], 0.0f);
            const float v0 = fmaxf(acc[i][j][1], 0.0f);
            const float k1 = fmaxf(acc[i][j][2], 0.0f);
            const float v1 = fmaxf(acc[i][j][3], 0.0f);
            g_V[r0 * HD + c] = v0;
            g_V[r1 * HD + c] = v1;
            s0 = fmaf(k0, qv[j], s0);
            s1 = fmaf(k1, qv[j], s1);
        }
        // reduce over tg quad (lane bits 0,1)
        s0 += __shfl_xor_sync(0xffffffffu, s0, 1);
        s0 += __shfl_xor_sync(0xffffffffu, s0, 2);
        s1 += __shfl_xor_sync(0xffffffffu, s1, 1);
        s1 += __shfl_xor_sync(0xffffffffu, s1, 2);
        if (tg == i) {
            stPart[wn][wm * 64 + i * 16 + g]     = s0;
            stPart[wn][wm * 64 + i * 16 + 8 + g] = s1;
        }
    }
    __syncthreads();
    if (tid < Bb_M)
        g_ST[(size_t)(m0 + tid) * HH + h] = stPart[0][tid] + stPart[1][tid];
}

// ---------------- scan combine step ----------------
__device__ __forceinline__ void scan_step(float& m, float& u, float& w, float s, float v)
{
    float mn = fmaxf(m, s);
    float sc = __expf(m - mn);
    float e  = __expf(s - mn);
    u = u * sc + e;
    w = w * sc + e * v;
    m = mn;
}

// ---------------- pass A: per-chunk aggregates ----------------
__global__ __launch_bounds__(64) void passA_kernel()
{
    const int chain = blockIdx.y;
    const int chunk = blockIdx.x;
    const int d     = threadIdx.x;
    const int b = chain >> 4, h = chain & 15;

    float m = -CUDART_INF_F, u = 0.0f, w = 0.0f;
    const int t0 = chunk * TC;
#pragma unroll 4
    for (int t = t0; t < t0 + TC; ++t) {
        const size_t row = (size_t)b * TT + t;
        float s = g_ST[row * HH + h];
        float v = g_V[row * HD + h * DD + d];
        scan_step(m, u, w, s, v);
    }
    const int idx = chain * NCH + chunk;
    if (d == 0) { g_AggM[idx] = m; g_AggU[idx] = u; }
    g_AggW[idx * DD + d] = w;
}

// ---------------- pass B: exclusive prefix over chunks ----------------
__global__ __launch_bounds__(64) void passB_kernel()
{
    const int chain = blockIdx.x;
    const int d     = threadIdx.x;
    float m = -CUDART_INF_F, u = 0.0f, w = 0.0f;
    for (int c = 0; c < NCH; ++c) {
        const int idx = chain * NCH + c;
        if (d == 0) { g_PreM[idx] = m; g_PreU[idx] = u; }
        g_PreW[idx * DD + d] = w;
        float mb = g_AggM[idx], ub = g_AggU[idx], wb = g_AggW[idx * DD + d];
        float mn = fmaxf(m, mb);
        float ea = __expf(m - mn);
        float eb = __expf(mb - mn);
        u = u * ea + ub * eb;
        w = w * ea + wb * eb;
        m = mn;
    }
}

// ---------------- pass C: re-scan with prefix, head-sum via atomics ----------------
__global__ __launch_bounds__(64) void passC_kernel(float* __restrict__ out)
{
    const int chain = blockIdx.y;
    const int chunk = blockIdx.x;
    const int d     = threadIdx.x;
    const int b = chain >> 4, h = chain & 15;

    const int idx = chain * NCH + chunk;
    float m = g_PreM[idx];
    float u = g_PreU[idx];
    float w = g_PreW[idx * DD + d];

    const int t0 = chunk * TC;
#pragma unroll 4
    for (int t = t0; t < t0 + TC; ++t) {
        const size_t row = (size_t)b * TT + t;
        float s = g_ST[row * HH + h];
        float v = g_V[row * HD + h * DD + d];
        scan_step(m, u, w, s, v);
        atomicAdd(out + row * DD + d, w / u);
    }
}

// ---------------- launch ----------------
extern "C" void kernel_launch(void* const* d_in, const int* in_sizes, int n_in,
                              void* d_out, int out_size)
{
    const float* inputs = (const float*)d_in[0];   // [4,4096,1024]
    const float* kvk    = (const float*)d_in[1];   // [1024,2048]
    const float* qk     = (const float*)d_in[2];   // [16,64]
    float* out = (float*)d_out;                    // [4,4096,64]

    zero_kernel<<<(out_size + 255) / 256, 256>>>(out, out_size);

    round_tf32_A<<<(MM * DIN / 4) / 256, 256>>>(inputs);
    {
        dim3 tg(NN / 32, DIN / 32);                // (64, 32)
        transW_kernel<<<tg, 256>>>(kvk);
    }

    dim3 ggrid(NN / Bb_N, MM / Bb_M);              // (16, 128)
    gemm_tc_kernel<<<ggrid, GT>>>(qk);

    dim3 sgrid(NCH, BB * HH);                      // (32, 64)
    passA_kernel<<<sgrid, 64>>>();
    passB_kernel<<<BB * HH, 64>>>();
    passC_kernel<<<sgrid, 64>>>(out);
}